// round 13
// baseline (speedup 1.0000x reference)
#include <cuda_runtime.h>

#define Bn 16
#define Cn 20
#define Hn 512
#define Wn 512
#define W4n (Wn / 4)
#define HWn (Hn * Wn)
#define HW4n (Hn * W4n)
#define CHWn (Cn * HWn)
#define HMASK (Hn - 1)
#define W4MASK (W4n - 1)

// Scratch (__device__ globals per allocation-free rule)
__device__ unsigned g_a1[Bn * HW4n];    // step-1 mask, 1 byte/pixel (0/1)
__device__ unsigned g_e1[Bn * HW4n];    // (world1 ch0 == 3) flag, packed
__device__ float4   g_d1[Bn * HW4n];    // world1 ch1 (density after step 1)
__device__ unsigned g_code[Bn * HW4n];  // per byte: a1[h] | a1[h+1]<<1 | a2[h]<<2 | a2[h+1]<<3

// exact 0/1-coefficient blend, BRANCHLESS: (1-a)(1-b)y + a*x + b*z
__device__ __forceinline__ float selv(bool a, bool b, float x, float y, float z) {
    float t = b ? z : y;
    t = a ? x : t;
    return (a && b) ? (x + z) : t;
}

__device__ __forceinline__ unsigned cmp3(float d, float df, float da, float dfa) {
    return (unsigned)(df >= d) & (unsigned)(da < d) & (unsigned)(dfa < d);
}

// ---------------- Kernel A: step-1 mask + step-1 ch0/ch1, 4-wide (R9 version) ----------------
__device__ __forceinline__ void kA_lane(
    float dm, float d, float dp, float dfm, float dfc, float dfp,
    float e0m, float e0c, float e0p,
    unsigned& a1, unsigned& e1, float& d1)
{
    a1 = (unsigned)(e0c == 3.0f) & cmp3(d, dfc, dm, dfm);
    unsigned b1 = (unsigned)(e0p == 3.0f) & cmp3(dp, dfp, d, dfc);
    float e1v = selv(a1 != 0u, b1 != 0u, e0m, e0c, e0p);
    d1        = selv(a1 != 0u, b1 != 0u, dm,  d,   dp);
    e1 = (unsigned)(e1v == 3.0f);
}

__global__ void kA(const float* __restrict__ world) {
    int idx = blockIdx.x * blockDim.x + threadIdx.x;   // b<<16 | h<<7 | w4
    int w4 = idx & W4MASK;
    int h  = (idx >> 7) & HMASK;
    int b  = idx >> 16;
    int hm = (h - 1) & HMASK, hp = (h + 1) & HMASK;
    int w4m = (w4 - 1) & W4MASK;

    const float4* c0 = (const float4*)(world + (long)b * CHWn);
    const float4* c1 = c0 + HW4n;

    float4 c1m = c1[hm * W4n + w4], c1c = c1[h * W4n + w4], c1p = c1[hp * W4n + w4];
    float4 c1mP = c1[hm * W4n + w4m], c1cP = c1[h * W4n + w4m], c1pP = c1[hp * W4n + w4m];
    float4 c0m = c0[hm * W4n + w4], c0c = c0[h * W4n + w4], c0p = c0[hp * W4n + w4];

    unsigned a1w = 0, e1w = 0;
    float4 d1v;
    unsigned a, e; float dd;

    kA_lane(c1m.x, c1c.x, c1p.x, c1mP.w, c1cP.w, c1pP.w, c0m.x, c0c.x, c0p.x, a, e, dd);
    a1w |= a; e1w |= e; d1v.x = dd;
    kA_lane(c1m.y, c1c.y, c1p.y, c1m.x, c1c.x, c1p.x, c0m.y, c0c.y, c0p.y, a, e, dd);
    a1w |= a << 8; e1w |= e << 8; d1v.y = dd;
    kA_lane(c1m.z, c1c.z, c1p.z, c1m.y, c1c.y, c1p.y, c0m.z, c0c.z, c0p.z, a, e, dd);
    a1w |= a << 16; e1w |= e << 16; d1v.z = dd;
    kA_lane(c1m.w, c1c.w, c1p.w, c1m.z, c1c.z, c1p.z, c0m.w, c0c.w, c0p.w, a, e, dd);
    a1w |= a << 24; e1w |= e << 24; d1v.w = dd;

    g_a1[idx] = a1w;
    g_e1[idx] = e1w;
    g_d1[idx] = d1v;
}

// ---------------- Kernel B: step-2 mask + packed per-pixel control byte ----------------
__global__ void kB() {
    int idx = blockIdx.x * blockDim.x + threadIdx.x;
    int w4 = idx & W4MASK;
    int h  = (idx >> 7) & HMASK;
    int b  = idx >> 16;
    int hm = (h - 1) & HMASK, hp = (h + 1) & HMASK;
    int w4p = (w4 + 1) & W4MASK;
    int base = b << 16;

    const float4* d1 = g_d1 + base;
    float4 dm = d1[hm * W4n + w4],  dc = d1[h * W4n + w4],  dp = d1[hp * W4n + w4];
    float4 dmN = d1[hm * W4n + w4p], dcN = d1[h * W4n + w4p], dpN = d1[hp * W4n + w4p];
    unsigned e1c = g_e1[idx];
    unsigned e1p = g_e1[base + hp * W4n + w4];
    unsigned a1c = g_a1[idx];
    unsigned a1p = g_a1[base + hp * W4n + w4];

    unsigned a2c = ((e1c)        & 1u) & cmp3(dc.x, dc.y, dm.x, dm.y);
    a2c |= (((e1c >> 8)  & 1u) & cmp3(dc.y, dc.z, dm.y, dm.z)) << 8;
    a2c |= (((e1c >> 16) & 1u) & cmp3(dc.z, dc.w, dm.z, dm.w)) << 16;
    a2c |= (((e1c >> 24) & 1u) & cmp3(dc.w, dcN.x, dm.w, dmN.x)) << 24;

    unsigned a2p = ((e1p)        & 1u) & cmp3(dp.x, dp.y, dc.x, dc.y);
    a2p |= (((e1p >> 8)  & 1u) & cmp3(dp.y, dp.z, dc.y, dc.z)) << 8;
    a2p |= (((e1p >> 16) & 1u) & cmp3(dp.z, dp.w, dc.z, dc.w)) << 16;
    a2p |= (((e1p >> 24) & 1u) & cmp3(dp.w, dpN.x, dc.w, dcN.x)) << 24;

    g_code[idx] = a1c | (a1p << 1) | (a2c << 2) | (a2p << 3);
}

// ---------------- Kernel C: two channels/thread, shared predicates ----------------
#define NCH 8
#define CHUNK (Hn / NCH)   // 64

// one predicate set (a, b, a&&b) feeds BOTH channels' selects
__device__ __forceinline__ void selp(bool a, bool b,
    float xA, float yA, float zA,
    float xB, float yB, float zB,
    float& oA, float& oB)
{
    bool ab = a && b;
    float tA = b ? zA : yA; tA = a ? xA : tA; oA = ab ? (xA + zA) : tA;
    float tB = b ? zB : yB; tB = a ? xB : tB; oB = ab ? (xB + zB) : tB;
}

// w1 stage: bits 0,1 of each byte of cw
__device__ __forceinline__ void w1pair(unsigned cw,
    const float4& aA, const float4& bA, const float4& cA,
    const float4& aB, const float4& bB, const float4& cB,
    float4& oA, float4& oB)
{
    selp(cw & 0x00000001u, cw & 0x00000002u, aA.x, bA.x, cA.x, aB.x, bB.x, cB.x, oA.x, oB.x);
    selp(cw & 0x00000100u, cw & 0x00000200u, aA.y, bA.y, cA.y, aB.y, bB.y, cB.y, oA.y, oB.y);
    selp(cw & 0x00010000u, cw & 0x00020000u, aA.z, bA.z, cA.z, aB.z, bB.z, cB.z, oA.z, oB.z);
    selp(cw & 0x01000000u, cw & 0x02000000u, aA.w, bA.w, cA.w, aB.w, bB.w, cB.w, oA.w, oB.w);
}
// out stage: bits 2,3 of each byte of cw
__device__ __forceinline__ void outpair(unsigned cw,
    const float4& aA, const float4& bA, const float4& cA,
    const float4& aB, const float4& bB, const float4& cB,
    float4& oA, float4& oB)
{
    selp(cw & 0x00000004u, cw & 0x00000008u, aA.x, bA.x, cA.x, aB.x, bB.x, cB.x, oA.x, oB.x);
    selp(cw & 0x00000400u, cw & 0x00000800u, aA.y, bA.y, cA.y, aB.y, bB.y, cB.y, oA.y, oB.y);
    selp(cw & 0x00040000u, cw & 0x00080000u, aA.z, bA.z, cA.z, aB.z, bB.z, cB.z, oA.z, oB.z);
    selp(cw & 0x04000000u, cw & 0x08000000u, aA.w, bA.w, cA.w, aB.w, bB.w, cB.w, oA.w, oB.w);
}

__global__ void __launch_bounds__(128) kC(const float* __restrict__ world,
                                          float* __restrict__ out) {
    int w4 = threadIdx.x;                 // 0..127 — full row of float4
    int h0 = blockIdx.y * CHUNK;
    int bc = blockIdx.z;                  // 0..159: b * 10 + channel-pair
    int b   = bc / (Cn / 2);
    int cp2 = bc - b * (Cn / 2);
    int c   = cp2 * 2;

    const float4* pA = (const float4*)(world + (long)b * CHWn + (long)c * HWn);
    const float4* pB = pA + HW4n;
    float4* qA = (float4*)(out + (long)b * CHWn + (long)c * HWn);
    float4* qB = qA + HW4n;
    const unsigned* ck = g_code + (b << 16);

    // rolling world rows h-2..h+2, both channels
    float4 rA0 = pA[((h0 - 2) & HMASK) * W4n + w4];
    float4 rA1 = pA[((h0 - 1) & HMASK) * W4n + w4];
    float4 rA2 = pA[h0 * W4n + w4];
    float4 rA3 = pA[((h0 + 1) & HMASK) * W4n + w4];
    float4 rA4 = pA[((h0 + 2) & HMASK) * W4n + w4];
    float4 rB0 = pB[((h0 - 2) & HMASK) * W4n + w4];
    float4 rB1 = pB[((h0 - 1) & HMASK) * W4n + w4];
    float4 rB2 = pB[h0 * W4n + w4];
    float4 rB3 = pB[((h0 + 1) & HMASK) * W4n + w4];
    float4 rB4 = pB[((h0 + 2) & HMASK) * W4n + w4];

    unsigned cm = ck[((h0 - 1) & HMASK) * W4n + w4];
    unsigned cc = ck[h0 * W4n + w4];
    unsigned cp = ck[((h0 + 1) & HMASK) * W4n + w4];

    float4 tA0, tA1, tA2, tB0, tB1, tB2;
    w1pair(cm, rA0, rA1, rA2, rB0, rB1, rB2, tA0, tB0);   // w1[h0-1]
    w1pair(cc, rA1, rA2, rA3, rB1, rB2, rB3, tA1, tB1);   // w1[h0]
    w1pair(cp, rA2, rA3, rA4, rB2, rB3, rB4, tA2, tB2);   // w1[h0+1]

    for (int hh = 0; hh < CHUNK; hh += 2) {
        int h = h0 + hh;
        // ---- front-batched loads for the next 2 rows, both channels (MLP=6) ----
        float4 LA0 = pA[((h + 3) & HMASK) * W4n + w4];
        float4 LB0 = pB[((h + 3) & HMASK) * W4n + w4];
        float4 LA1 = pA[((h + 4) & HMASK) * W4n + w4];
        float4 LB1 = pB[((h + 4) & HMASK) * W4n + w4];
        unsigned C0 = ck[((h + 2) & HMASK) * W4n + w4];
        unsigned C1 = ck[((h + 3) & HMASK) * W4n + w4];

        // row h
        float4 oA, oB;
        outpair(cc, tA0, tA1, tA2, tB0, tB1, tB2, oA, oB);
        __stcs(qA + h * W4n + w4, oA);
        __stcs(qB + h * W4n + w4, oB);
        rA0 = rA1; rA1 = rA2; rA2 = rA3; rA3 = rA4; rA4 = LA0;
        rB0 = rB1; rB1 = rB2; rB2 = rB3; rB3 = rB4; rB4 = LB0;
        tA0 = tA1; tA1 = tA2; tB0 = tB1; tB1 = tB2;
        w1pair(C0, rA2, rA3, rA4, rB2, rB3, rB4, tA2, tB2);   // w1[h+2]
        cc = cp; cp = C0;

        // row h+1
        outpair(cc, tA0, tA1, tA2, tB0, tB1, tB2, oA, oB);
        __stcs(qA + (h + 1) * W4n + w4, oA);
        __stcs(qB + (h + 1) * W4n + w4, oB);
        rA0 = rA1; rA1 = rA2; rA2 = rA3; rA3 = rA4; rA4 = LA1;
        rB0 = rB1; rB1 = rB2; rB2 = rB3; rB3 = rB4; rB4 = LB1;
        tA0 = tA1; tA1 = tA2; tB0 = tB1; tB1 = tB2;
        w1pair(C1, rA2, rA3, rA4, rB2, rB3, rB4, tA2, tB2);   // w1[h+3]
        cc = cp; cp = C1;
    }
}

extern "C" void kernel_launch(void* const* d_in, const int* in_sizes, int n_in,
                              void* d_out, int out_size) {
    const float* world = (const float*)d_in[0];   // (16,20,512,512) fp32
    float* out = (float*)d_out;

    int nvec = Bn * HW4n;                 // 1,048,576
    kA<<<nvec / 256, 256>>>(world);
    kB<<<nvec / 256, 256>>>();

    dim3 grid(1, NCH, Bn * (Cn / 2));     // (1, 8, 160)
    kC<<<grid, 128>>>(world, out);
}

// round 14
// speedup vs baseline: 1.2093x; 1.2093x over previous
#include <cuda_runtime.h>

#define Bn 16
#define Cn 20
#define Hn 512
#define Wn 512
#define W4n (Wn / 4)
#define HWn (Hn * Wn)
#define HW4n (Hn * W4n)
#define CHWn (Cn * HWn)
#define HMASK (Hn - 1)
#define W4MASK (W4n - 1)

// Scratch (__device__ globals per allocation-free rule)
__device__ unsigned g_a1[Bn * HW4n];    // step-1 mask, 1 byte/pixel (0/1)
__device__ unsigned g_e1[Bn * HW4n];    // (world1 ch0 == 3) flag, packed
__device__ float4   g_d1[Bn * HW4n];    // world1 ch1 (density after step 1)
__device__ unsigned g_code[Bn * HW4n];  // per byte: a1[h] | a1[h+1]<<1 | a2[h]<<2 | a2[h+1]<<3

// exact 0/1-coefficient blend, BRANCHLESS: (1-a)(1-b)y + a*x + b*z
__device__ __forceinline__ float selv(bool a, bool b, float x, float y, float z) {
    float t = b ? z : y;
    t = a ? x : t;
    return (a && b) ? (x + z) : t;
}

__device__ __forceinline__ unsigned cmp3(float d, float df, float da, float dfa) {
    return (unsigned)(df >= d) & (unsigned)(da < d) & (unsigned)(dfa < d);
}

// ---------------- Kernel A: step-1 mask + step-1 ch0/ch1, 4-wide (R9 version) ----------------
__device__ __forceinline__ void kA_lane(
    float dm, float d, float dp, float dfm, float dfc, float dfp,
    float e0m, float e0c, float e0p,
    unsigned& a1, unsigned& e1, float& d1)
{
    a1 = (unsigned)(e0c == 3.0f) & cmp3(d, dfc, dm, dfm);
    unsigned b1 = (unsigned)(e0p == 3.0f) & cmp3(dp, dfp, d, dfc);
    float e1v = selv(a1 != 0u, b1 != 0u, e0m, e0c, e0p);
    d1        = selv(a1 != 0u, b1 != 0u, dm,  d,   dp);
    e1 = (unsigned)(e1v == 3.0f);
}

__global__ void kA(const float* __restrict__ world) {
    int idx = blockIdx.x * blockDim.x + threadIdx.x;   // b<<16 | h<<7 | w4
    int w4 = idx & W4MASK;
    int h  = (idx >> 7) & HMASK;
    int b  = idx >> 16;
    int hm = (h - 1) & HMASK, hp = (h + 1) & HMASK;
    int w4m = (w4 - 1) & W4MASK;

    const float4* c0 = (const float4*)(world + (long)b * CHWn);
    const float4* c1 = c0 + HW4n;

    float4 c1m = c1[hm * W4n + w4], c1c = c1[h * W4n + w4], c1p = c1[hp * W4n + w4];
    float4 c1mP = c1[hm * W4n + w4m], c1cP = c1[h * W4n + w4m], c1pP = c1[hp * W4n + w4m];
    float4 c0m = c0[hm * W4n + w4], c0c = c0[h * W4n + w4], c0p = c0[hp * W4n + w4];

    unsigned a1w = 0, e1w = 0;
    float4 d1v;
    unsigned a, e; float dd;

    kA_lane(c1m.x, c1c.x, c1p.x, c1mP.w, c1cP.w, c1pP.w, c0m.x, c0c.x, c0p.x, a, e, dd);
    a1w |= a; e1w |= e; d1v.x = dd;
    kA_lane(c1m.y, c1c.y, c1p.y, c1m.x, c1c.x, c1p.x, c0m.y, c0c.y, c0p.y, a, e, dd);
    a1w |= a << 8; e1w |= e << 8; d1v.y = dd;
    kA_lane(c1m.z, c1c.z, c1p.z, c1m.y, c1c.y, c1p.y, c0m.z, c0c.z, c0p.z, a, e, dd);
    a1w |= a << 16; e1w |= e << 16; d1v.z = dd;
    kA_lane(c1m.w, c1c.w, c1p.w, c1m.z, c1c.z, c1p.z, c0m.w, c0c.w, c0p.w, a, e, dd);
    a1w |= a << 24; e1w |= e << 24; d1v.w = dd;

    g_a1[idx] = a1w;
    g_e1[idx] = e1w;
    g_d1[idx] = d1v;
}

// ---------------- Kernel B: step-2 mask + packed per-pixel control byte ----------------
__global__ void kB() {
    int idx = blockIdx.x * blockDim.x + threadIdx.x;
    int w4 = idx & W4MASK;
    int h  = (idx >> 7) & HMASK;
    int b  = idx >> 16;
    int hm = (h - 1) & HMASK, hp = (h + 1) & HMASK;
    int w4p = (w4 + 1) & W4MASK;
    int base = b << 16;

    const float4* d1 = g_d1 + base;
    float4 dm = d1[hm * W4n + w4],  dc = d1[h * W4n + w4],  dp = d1[hp * W4n + w4];
    float4 dmN = d1[hm * W4n + w4p], dcN = d1[h * W4n + w4p], dpN = d1[hp * W4n + w4p];
    unsigned e1c = g_e1[idx];
    unsigned e1p = g_e1[base + hp * W4n + w4];
    unsigned a1c = g_a1[idx];
    unsigned a1p = g_a1[base + hp * W4n + w4];

    unsigned a2c = ((e1c)        & 1u) & cmp3(dc.x, dc.y, dm.x, dm.y);
    a2c |= (((e1c >> 8)  & 1u) & cmp3(dc.y, dc.z, dm.y, dm.z)) << 8;
    a2c |= (((e1c >> 16) & 1u) & cmp3(dc.z, dc.w, dm.z, dm.w)) << 16;
    a2c |= (((e1c >> 24) & 1u) & cmp3(dc.w, dcN.x, dm.w, dmN.x)) << 24;

    unsigned a2p = ((e1p)        & 1u) & cmp3(dp.x, dp.y, dc.x, dc.y);
    a2p |= (((e1p >> 8)  & 1u) & cmp3(dp.y, dp.z, dc.y, dc.z)) << 8;
    a2p |= (((e1p >> 16) & 1u) & cmp3(dp.z, dp.w, dc.z, dc.w)) << 16;
    a2p |= (((e1p >> 24) & 1u) & cmp3(dp.w, dpN.x, dc.w, dcN.x)) << 24;

    g_code[idx] = a1c | (a1p << 1) | (a2c << 2) | (a2p << 3);
}

// ---------------- Kernel C: fused two-step apply, pointer-increment main loop ----------------
#define NCH 8
#define CHUNK (Hn / NCH)   // 64

__device__ __forceinline__ float4 w1vec(unsigned cw, float4 a, float4 b, float4 c) {
    float4 o;
    o.x = selv(cw & 0x00000001u, cw & 0x00000002u, a.x, b.x, c.x);
    o.y = selv(cw & 0x00000100u, cw & 0x00000200u, a.y, b.y, c.y);
    o.z = selv(cw & 0x00010000u, cw & 0x00020000u, a.z, b.z, c.z);
    o.w = selv(cw & 0x01000000u, cw & 0x02000000u, a.w, b.w, c.w);
    return o;
}
__device__ __forceinline__ float4 outvec(unsigned cw, float4 a, float4 b, float4 c) {
    float4 o;
    o.x = selv(cw & 0x00000004u, cw & 0x00000008u, a.x, b.x, c.x);
    o.y = selv(cw & 0x00000400u, cw & 0x00000800u, a.y, b.y, c.y);
    o.z = selv(cw & 0x00040000u, cw & 0x00080000u, a.z, b.z, c.z);
    o.w = selv(cw & 0x04000000u, cw & 0x08000000u, a.w, b.w, c.w);
    return o;
}

// one row: store out[h], then roll windows using fresh load L / code C
#define ROW1(L, C, QP)                                   \
    __stcs((QP), outvec(cc, t0, t1, t2));                \
    r0 = r1; r1 = r2; r2 = r3; r3 = r4; r4 = (L);        \
    t0 = t1; t1 = t2; t2 = w1vec((C), r2, r3, r4);       \
    cc = cp; cp = (C);

__global__ void __launch_bounds__(128, 8) kC(const float* __restrict__ world,
                                             float* __restrict__ out) {
    int w4 = threadIdx.x;                 // 0..127 — full row of float4
    int h0 = blockIdx.y * CHUNK;
    int bc = blockIdx.z;
    int b = bc / Cn;
    int c = bc - b * Cn;

    const float4* p = (const float4*)(world + (long)b * CHWn + (long)c * HWn) + w4;
    float4*       q = (float4*)(out + (long)b * CHWn + (long)c * HWn) + w4;
    const unsigned* ck = g_code + (b << 16) + w4;

    // masked prologue (handles y=0 negative rows)
    float4 r0 = p[((h0 - 2) & HMASK) * W4n];
    float4 r1 = p[((h0 - 1) & HMASK) * W4n];
    float4 r2 = p[h0 * W4n];
    float4 r3 = p[((h0 + 1) & HMASK) * W4n];
    float4 r4 = p[((h0 + 2) & HMASK) * W4n];

    unsigned cm = ck[((h0 - 1) & HMASK) * W4n];
    unsigned cc = ck[h0 * W4n];
    unsigned cp = ck[((h0 + 1) & HMASK) * W4n];

    float4 t0 = w1vec(cm, r0, r1, r2);   // w1[h0-1]
    float4 t1 = w1vec(cc, r1, r2, r3);   // w1[h0]
    float4 t2 = w1vec(cp, r2, r3, r4);   // w1[h0+1]

    if (blockIdx.y != NCH - 1) {
        // interior chunks: loop loads touch rows h0+3 .. h0+66 <= 450 < 512 — no wrap.
        // Pure pointer-increment addressing lets ptxas emit LDG [R+imm].
        const float4*   pl = p  + (h0 + 3) * W4n;
        const unsigned* cl = ck + (h0 + 2) * W4n;
        float4*         qs = q  + h0 * W4n;
        for (int hh = 0; hh < CHUNK; hh += 4) {
            float4 L0 = pl[0 * W4n], L1 = pl[1 * W4n], L2 = pl[2 * W4n], L3 = pl[3 * W4n];
            unsigned C0 = cl[0 * W4n], C1 = cl[1 * W4n], C2 = cl[2 * W4n], C3 = cl[3 * W4n];
            ROW1(L0, C0, qs + 0 * W4n)
            ROW1(L1, C1, qs + 1 * W4n)
            ROW1(L2, C2, qs + 2 * W4n)
            ROW1(L3, C3, qs + 3 * W4n)
            pl += 4 * W4n; cl += 4 * W4n; qs += 4 * W4n;
        }
    } else {
        // last chunk: loads wrap past row 511 — keep masked addressing (stores never wrap)
        for (int hh = 0; hh < CHUNK; hh += 4) {
            int h = h0 + hh;
            float4 L0 = p[((h + 3) & HMASK) * W4n];
            float4 L1 = p[((h + 4) & HMASK) * W4n];
            float4 L2 = p[((h + 5) & HMASK) * W4n];
            float4 L3 = p[((h + 6) & HMASK) * W4n];
            unsigned C0 = ck[((h + 2) & HMASK) * W4n];
            unsigned C1 = ck[((h + 3) & HMASK) * W4n];
            unsigned C2 = ck[((h + 4) & HMASK) * W4n];
            unsigned C3 = ck[((h + 5) & HMASK) * W4n];
            ROW1(L0, C0, q + (h + 0) * W4n)
            ROW1(L1, C1, q + (h + 1) * W4n)
            ROW1(L2, C2, q + (h + 2) * W4n)
            ROW1(L3, C3, q + (h + 3) * W4n)
        }
    }
}

extern "C" void kernel_launch(void* const* d_in, const int* in_sizes, int n_in,
                              void* d_out, int out_size) {
    const float* world = (const float*)d_in[0];   // (16,20,512,512) fp32
    float* out = (float*)d_out;

    int nvec = Bn * HW4n;                 // 1,048,576
    kA<<<nvec / 256, 256>>>(world);
    kB<<<nvec / 256, 256>>>();

    dim3 grid(1, NCH, Bn * Cn);           // (1, 8, 320)
    kC<<<grid, 128>>>(world, out);
}